// round 4
// baseline (speedup 1.0000x reference)
#include <cuda_runtime.h>
#include <cuda_bf16.h>
#include <cstdint>

#define NINST 64
#define HDIM 100
#define WDIM 152
#define HW 15200
#define NB 32
#define NKP 17
#define ATTN_LEN 2737
#define KDIM 2304
#define KSPLIT 8
#define KCHUNK (KDIM / KSPLIT)   // 288
#define IPB 16                   // instances per mlp CTA
#define IG  (NINST / IPB)        // 4
#define NTILE 119                // ceil(HW/128)
#define NFRAG 88                 // B fragment float2-entries per instance

typedef unsigned long long ull;

__device__ float g_attns[NINST * ATTN_LEN];
__device__ float g_part[KSPLIT * NINST * ATTN_LEN];
__device__ uint2 g_bfrag[NINST * NFRAG * 32];

// ---------------- packed f32x2 helpers (gemm) ----------------
__device__ __forceinline__ ull pack2(float x, float y) {
    ull r; asm("mov.b64 %0, {%1, %2};" : "=l"(r) : "f"(x), "f"(y)); return r;
}
__device__ __forceinline__ ull ffma2(ull a, ull b, ull c) {
    ull d; asm("fma.rn.f32x2 %0, %1, %2, %3;" : "=l"(d) : "l"(a), "l"(b), "l"(c)); return d;
}
__device__ __forceinline__ float2 unpack2(ull v) {
    float2 r; asm("mov.b64 {%0, %1}, %2;" : "=f"(r.x), "=f"(r.y) : "l"(v)); return r;
}

// ---------------- tf32 helpers ----------------
__device__ __forceinline__ uint32_t f2tf32(float x) {
    uint32_t r; asm("cvt.rna.tf32.f32 %0, %1;" : "=r"(r) : "f"(x)); return r;
}
__device__ __forceinline__ void tf32_split(float x, uint32_t& hi, uint32_t& lo) {
    hi = f2tf32(x);
    lo = f2tf32(x - __uint_as_float(hi));
}
__device__ __forceinline__ void mma_tf32(float* c, const uint32_t* a, uint2 b) {
    asm volatile(
        "mma.sync.aligned.m16n8k8.row.col.f32.tf32.tf32.f32 "
        "{%0,%1,%2,%3}, {%4,%5,%6,%7}, {%8,%9}, {%0,%1,%2,%3};"
        : "+f"(c[0]), "+f"(c[1]), "+f"(c[2]), "+f"(c[3])
        : "r"(a[0]), "r"(a[1]), "r"(a[2]), "r"(a[3]), "r"(b.x), "r"(b.y));
}

// ---------------------------------------------------------------------------
// Kernel A1: split-K partial GEMM (unchanged from R2).
// ---------------------------------------------------------------------------
__global__ __launch_bounds__(128) void gemm_partial(const float* __restrict__ A,
                                                    const float* __restrict__ Wm) {
    __shared__ __align__(16) float As[32][64];
    __shared__ __align__(16) float Ws[32][16];
    int tid = threadIdx.x;
    int jblk = blockIdx.x * 16;
    int kbase = blockIdx.y * KCHUNK;

    int an = tid >> 1;
    int ak = (tid & 1) * 16;
    int wj = tid >> 3;
    int wk = (tid & 7) * 4;
    int n0 = (tid & 15) * 4;
    int j0 = (tid >> 4) * 2;

    ull acc2[2][2];
    acc2[0][0] = acc2[0][1] = acc2[1][0] = acc2[1][1] = 0ULL;

    for (int k0 = kbase; k0 < kbase + KCHUNK; k0 += 32) {
        __syncthreads();
        const float4* ap = (const float4*)(A + (size_t)an * KDIM + k0 + ak);
#pragma unroll
        for (int v = 0; v < 4; v++) {
            float4 t = ap[v];
            As[ak + v * 4 + 0][an] = t.x;
            As[ak + v * 4 + 1][an] = t.y;
            As[ak + v * 4 + 2][an] = t.z;
            As[ak + v * 4 + 3][an] = t.w;
        }
        {
            int j = jblk + wj;
            float4 t = make_float4(0.f, 0.f, 0.f, 0.f);
            if (j < ATTN_LEN)
                t = *(const float4*)(Wm + (size_t)j * KDIM + k0 + wk);
            Ws[wk + 0][wj] = t.x;
            Ws[wk + 1][wj] = t.y;
            Ws[wk + 2][wj] = t.z;
            Ws[wk + 3][wj] = t.w;
        }
        __syncthreads();
#pragma unroll
        for (int kk = 0; kk < 32; kk++) {
            ulonglong2 a2 = *(const ulonglong2*)&As[kk][n0];
            float2 wf = *(const float2*)&Ws[kk][j0];
            ull wx = pack2(wf.x, wf.x);
            ull wy = pack2(wf.y, wf.y);
            acc2[0][0] = ffma2(a2.x, wx, acc2[0][0]);
            acc2[0][1] = ffma2(a2.x, wy, acc2[0][1]);
            acc2[1][0] = ffma2(a2.y, wx, acc2[1][0]);
            acc2[1][1] = ffma2(a2.y, wy, acc2[1][1]);
        }
    }
    float* outp = g_part + (size_t)blockIdx.y * NINST * ATTN_LEN;
#pragma unroll
    for (int p = 0; p < 2; p++) {
#pragma unroll
        for (int dj = 0; dj < 2; dj++) {
            int j = jblk + j0 + dj;
            if (j < ATTN_LEN) {
                float2 u = unpack2(acc2[p][dj]);
                outp[(size_t)(n0 + 2 * p)     * ATTN_LEN + j] = u.x;
                outp[(size_t)(n0 + 2 * p + 1) * ATTN_LEN + j] = u.y;
            }
        }
    }
}

// ---------------------------------------------------------------------------
// Kernel A2: deterministic reduce over KSPLIT partials + bias.
// ---------------------------------------------------------------------------
__global__ __launch_bounds__(256) void reduce_attns(const float* __restrict__ bias) {
    int idx = blockIdx.x * 256 + threadIdx.x;
    if (idx >= NINST * ATTN_LEN) return;
    float s = 0.f;
#pragma unroll
    for (int p = 0; p < KSPLIT; p++) s += g_part[(size_t)p * NINST * ATTN_LEN + idx];
    g_attns[idx] = s + bias[idx % ATTN_LEN];
}

// ---------------------------------------------------------------------------
// Kernel A3: build per-lane B fragments (tf32 hi/lo) for mma.sync.
// Fragment entry layout per instance: [fragIdx(88)][lane(32)] of uint2
//   fragIdx = layerBase + (nt*4 + kt)*2 + split   (split: 0=hi, 1=lo)
//   layerBase: L1=0 (nt 0..3), L2=32 (nt 0..3), L3=64 (nt 0..2)
// Entry value: reg0 = W[o][c], reg1 = W[o][c+4], with
//   o = nt*8 + (lane>>2),  c = kt*8 + (lane&3)
// ---------------------------------------------------------------------------
__global__ __launch_bounds__(256) void build_bfrag() {
    int n = blockIdx.x;
    const float* row = g_attns + (size_t)n * ATTN_LEN;
    uint2* dst = g_bfrag + (size_t)n * NFRAG * 32;

    for (int e = threadIdx.x; e < NFRAG * 32; e += 256) {
        int lane = e & 31;
        int fragIdx = e >> 5;
        int s = fragIdx & 1;
        int q = fragIdx >> 1;           // 0..43
        int layer, nt, kt;
        if (q < 16)      { layer = 0; nt = q >> 2;        kt = q & 3; }
        else if (q < 32) { layer = 1; nt = (q - 16) >> 2; kt = q & 3; }
        else             { layer = 2; nt = (q - 32) >> 2; kt = q & 3; }

        int o = nt * 8 + (lane >> 2);
        int c = kt * 8 + (lane & 3);

        float x0 = 0.f, x1 = 0.f;
        if (layer == 0) {
            x0 = row[o * 34 + (c + 2)];
            x1 = row[o * 34 + (c + 4 + 2)];
        } else if (layer == 1) {
            x0 = row[1120 + o * 32 + c];
            x1 = row[1120 + o * 32 + c + 4];
        } else if (o < NKP) {
            x0 = row[2176 + o * 32 + c];
            x1 = row[2176 + o * 32 + c + 4];
        }
        uint32_t h0, l0, h1, l1;
        tf32_split(x0, h0, l0);
        tf32_split(x1, h1, l1);
        dst[e] = s ? make_uint2(l0, l1) : make_uint2(h0, h1);
    }
}

// ---------------------------------------------------------------------------
// Kernel B: MLP via mma.sync tf32 (3xTF32). 256 threads = 8 independent warps,
// each warp owns 16 pixels; CTA covers 128 px x 16 instances (looped).
// Bases A-fragments built once per warp, reused across instances.
// ---------------------------------------------------------------------------
__device__ __forceinline__ void frags_from_hbuf(const float* hb, int lane,
                                                uint32_t* ah, uint32_t* al) {
    int g = lane >> 2, tig = lane & 3;
#pragma unroll
    for (int kt = 0; kt < 4; kt++) {
#pragma unroll
        for (int r = 0; r < 4; r++) {
            int rowi = g + ((r & 1) << 3);
            int c = kt * 8 + tig + ((r >> 1) << 2);
            tf32_split(hb[rowi * 33 + c], ah[kt * 4 + r], al[kt * 4 + r]);
        }
    }
}

__global__ __launch_bounds__(256, 2) void mlp_mma(const float* __restrict__ bases_full,
                                                  const float* __restrict__ locations,
                                                  const float* __restrict__ sizes,
                                                  const int* __restrict__ fpn_levels,
                                                  float* __restrict__ out) {
    __shared__ float hbuf_all[8][16 * 33];

    int tid = threadIdx.x;
    int warp = tid >> 5;
    int lane = tid & 31;
    int g = lane >> 2, tig = lane & 3;

    int pxb = blockIdx.x * 128 + warp * 16;
    if (pxb >= HW) return;                 // HW % 16 == 0: whole-warp granularity

    float* hb = hbuf_all[warp];

    int px0 = pxb + g;
    int px1 = px0 + 8;
    float gx0 = (float)(px0 % WDIM) * 8.f + 4.f;
    float gy0 = (float)(px0 / WDIM) * 8.f + 4.f;
    float gx1 = (float)(px1 % WDIM) * 8.f + 4.f;
    float gy1 = (float)(px1 / WDIM) * 8.f + 4.f;

    // ---- bases -> A1 fragments (persist across instances) ----
    uint32_t a1h[16], a1l[16];
#pragma unroll
    for (int kt = 0; kt < 4; kt++) {
#pragma unroll
        for (int r = 0; r < 4; r++) {
            int rowi = g + ((r & 1) << 3);
            int c = kt * 8 + tig + ((r >> 1) << 2);
            float x = bases_full[(size_t)c * HW + pxb + rowi];
            tf32_split(x, a1h[kt * 4 + r], a1l[kt * 4 + r]);
        }
    }

    int nbase = blockIdx.y * IPB;
    for (int ii = 0; ii < IPB; ii++) {
        int n = nbase + ii;
        const uint2* bf = g_bfrag + (size_t)n * NFRAG * 32;
        const float* row = g_attns + (size_t)n * ATTN_LEN;

        float invr = 1.f / sizes[fpn_levels[n]];
        float lx = locations[2 * n], ly = locations[2 * n + 1];
        float ox0 = (lx - gx0) * invr, oy0 = (ly - gy0) * invr;
        float ox1 = (lx - gx1) * invr, oy1 = (ly - gy1) * invr;

        float cc[4][4];
        uint32_t a2h[16], a2l[16];

        // ================= layer 1 =================
#pragma unroll
        for (int nt = 0; nt < 4; nt++) {
            cc[nt][0] = cc[nt][1] = cc[nt][2] = cc[nt][3] = 0.f;
#pragma unroll
            for (int kt = 0; kt < 4; kt++) {
                uint2 bh = bf[((nt * 4 + kt) * 2 + 0) * 32 + lane];
                uint2 bl = bf[((nt * 4 + kt) * 2 + 1) * 32 + lane];
                mma_tf32(cc[nt], &a1h[kt * 4], bh);
                mma_tf32(cc[nt], &a1h[kt * 4], bl);
                mma_tf32(cc[nt], &a1l[kt * 4], bh);
            }
        }
        // epilogue: fold offsets + bias, relu, stash to hbuf
#pragma unroll
        for (int nt = 0; nt < 4; nt++) {
            int o0 = nt * 8 + 2 * tig, o1 = o0 + 1;
            float wx0 = row[o0 * 34], wy0 = row[o0 * 34 + 1], bb0 = row[1088 + o0];
            float wx1 = row[o1 * 34], wy1 = row[o1 * 34 + 1], bb1 = row[1088 + o1];
            hb[g * 33 + o0]       = fmaxf(cc[nt][0] + wx0 * ox0 + wy0 * oy0 + bb0, 0.f);
            hb[g * 33 + o1]       = fmaxf(cc[nt][1] + wx1 * ox0 + wy1 * oy0 + bb1, 0.f);
            hb[(g + 8) * 33 + o0] = fmaxf(cc[nt][2] + wx0 * ox1 + wy0 * oy1 + bb0, 0.f);
            hb[(g + 8) * 33 + o1] = fmaxf(cc[nt][3] + wx1 * ox1 + wy1 * oy1 + bb1, 0.f);
        }
        __syncwarp();
        frags_from_hbuf(hb, lane, a2h, a2l);
        __syncwarp();

        // ================= layer 2 =================
#pragma unroll
        for (int nt = 0; nt < 4; nt++) {
            cc[nt][0] = cc[nt][1] = cc[nt][2] = cc[nt][3] = 0.f;
#pragma unroll
            for (int kt = 0; kt < 4; kt++) {
                uint2 bh = bf[(32 + (nt * 4 + kt) * 2 + 0) * 32 + lane];
                uint2 bl = bf[(32 + (nt * 4 + kt) * 2 + 1) * 32 + lane];
                mma_tf32(cc[nt], &a2h[kt * 4], bh);
                mma_tf32(cc[nt], &a2h[kt * 4], bl);
                mma_tf32(cc[nt], &a2l[kt * 4], bh);
            }
        }
#pragma unroll
        for (int nt = 0; nt < 4; nt++) {
            int o0 = nt * 8 + 2 * tig, o1 = o0 + 1;
            float bb0 = row[2144 + o0], bb1 = row[2144 + o1];
            hb[g * 33 + o0]       = fmaxf(cc[nt][0] + bb0, 0.f);
            hb[g * 33 + o1]       = fmaxf(cc[nt][1] + bb1, 0.f);
            hb[(g + 8) * 33 + o0] = fmaxf(cc[nt][2] + bb0, 0.f);
            hb[(g + 8) * 33 + o1] = fmaxf(cc[nt][3] + bb1, 0.f);
        }
        __syncwarp();
        frags_from_hbuf(hb, lane, a2h, a2l);
        __syncwarp();

        // ================= layer 3 (N padded to 24, write o<17) =================
#pragma unroll
        for (int nt = 0; nt < 3; nt++) {
            cc[nt][0] = cc[nt][1] = cc[nt][2] = cc[nt][3] = 0.f;
#pragma unroll
            for (int kt = 0; kt < 4; kt++) {
                uint2 bh = bf[(64 + (nt * 4 + kt) * 2 + 0) * 32 + lane];
                uint2 bl = bf[(64 + (nt * 4 + kt) * 2 + 1) * 32 + lane];
                mma_tf32(cc[nt], &a2h[kt * 4], bh);
                mma_tf32(cc[nt], &a2h[kt * 4], bl);
                mma_tf32(cc[nt], &a2l[kt * 4], bh);
            }
        }
        float* ob = out + (size_t)n * NKP * HW;
#pragma unroll
        for (int nt = 0; nt < 3; nt++) {
            int o0 = nt * 8 + 2 * tig, o1 = o0 + 1;
            if (o0 < NKP) {
                float bb0 = row[2720 + o0];
                ob[(size_t)o0 * HW + px0] = cc[nt][0] + bb0;
                ob[(size_t)o0 * HW + px1] = cc[nt][2] + bb0;
            }
            if (o1 < NKP) {
                float bb1 = row[2720 + o1];
                ob[(size_t)o1 * HW + px0] = cc[nt][1] + bb1;
                ob[(size_t)o1 * HW + px1] = cc[nt][3] + bb1;
            }
        }
        __syncwarp();
    }
}

// ---------------------------------------------------------------------------
// Kernel C: per (n, kp) argmax over HW (first-index tie-break), then gather.
// ---------------------------------------------------------------------------
__global__ __launch_bounds__(256) void argmax_kernel(float* __restrict__ out,
                                                     const float* __restrict__ bases_full) {
    int pair = blockIdx.x;
    int k = pair % NKP;
    const float4* lg = (const float4*)(out + (size_t)pair * HW);
    int tid = threadIdx.x;

    float best = -3.4e38f;
    int bi = 0;
    for (int q = tid; q < HW / 4; q += 256) {
        float4 v = lg[q];
        int i0 = q * 4;
        if (v.x > best) { best = v.x; bi = i0; }
        if (v.y > best) { best = v.y; bi = i0 + 1; }
        if (v.z > best) { best = v.z; bi = i0 + 2; }
        if (v.w > best) { best = v.w; bi = i0 + 3; }
    }

    __shared__ float sv[256];
    __shared__ int si[256];
    sv[tid] = best;
    si[tid] = bi;
    __syncthreads();
#pragma unroll
    for (int s = 128; s > 0; s >>= 1) {
        if (tid < s) {
            float ov = sv[tid + s]; int oi = si[tid + s];
            if (ov > sv[tid] || (ov == sv[tid] && oi < si[tid])) {
                sv[tid] = ov; si[tid] = oi;
            }
        }
        __syncthreads();
    }
    if (tid == 0) {
        int i = si[0];
        float gx = (float)(i % WDIM) * 8.f + 4.f;
        float gy = (float)(i / WDIM) * 8.f + 4.f;
        float* kp = out + (size_t)NINST * NKP * HW + (size_t)pair * 2;
        kp[0] = bases_full[(size_t)(NB + 2 * k)     * HW + i] + gx;
        kp[1] = bases_full[(size_t)(NB + 2 * k + 1) * HW + i] + gy;
    }
}

// ---------------------------------------------------------------------------
extern "C" void kernel_launch(void* const* d_in, const int* in_sizes, int n_in,
                              void* d_out, int out_size) {
    const float* bases_full = (const float*)d_in[0];
    const float* top_feats  = (const float*)d_in[1];
    const float* locations  = (const float*)d_in[2];
    const float* atten_W    = (const float*)d_in[3];
    const float* atten_b    = (const float*)d_in[4];
    const float* sizes      = (const float*)d_in[5];
    const int*   fpn_levels = (const int*)d_in[6];
    float* out = (float*)d_out;

    gemm_partial<<<dim3((ATTN_LEN + 15) / 16, KSPLIT), 128>>>(top_feats, atten_W);
    reduce_attns<<<(NINST * ATTN_LEN + 255) / 256, 256>>>(atten_b);
    build_bfrag<<<NINST, 256>>>();

    mlp_mma<<<dim3(NTILE, IG), 256>>>(bases_full, locations, sizes, fpn_levels, out);

    argmax_kernel<<<NINST * NKP, 256>>>(out, bases_full);
}

// round 5
// speedup vs baseline: 1.2576x; 1.2576x over previous
#include <cuda_runtime.h>
#include <cuda_bf16.h>
#include <cstdint>

#define NINST 64
#define HDIM 100
#define WDIM 152
#define HW 15200
#define NB 32
#define NKP 17
#define ATTN_LEN 2737
#define KDIM 2304
#define KSPLIT 8
#define KCHUNK (KDIM / KSPLIT)   // 288
#define IPB 4                    // instances per mlp CTA
#define IGY (NINST / IPB)        // 16
#define GX 60                    // ceil(HW / 256)
#define NQ 44                    // uint4 B-fragment entries per instance (per lane)
#define BFRAG_INST (NQ * 32)     // 1408 uint4 per instance

typedef unsigned long long ull;

__device__ float g_attns[NINST * ATTN_LEN];
__device__ float g_part[KSPLIT * NINST * ATTN_LEN];
__device__ uint4 g_bfrag[NINST * BFRAG_INST];

// ---------------- packed f32x2 helpers (gemm) ----------------
__device__ __forceinline__ ull pack2(float x, float y) {
    ull r; asm("mov.b64 %0, {%1, %2};" : "=l"(r) : "f"(x), "f"(y)); return r;
}
__device__ __forceinline__ ull ffma2(ull a, ull b, ull c) {
    ull d; asm("fma.rn.f32x2 %0, %1, %2, %3;" : "=l"(d) : "l"(a), "l"(b), "l"(c)); return d;
}
__device__ __forceinline__ float2 unpack2(ull v) {
    float2 r; asm("mov.b64 {%0, %1}, %2;" : "=f"(r.x), "=f"(r.y) : "l"(v)); return r;
}

// ---------------- tf32 helpers ----------------
__device__ __forceinline__ uint32_t f2tf32(float x) {
    uint32_t r; asm("cvt.rna.tf32.f32 %0, %1;" : "=r"(r) : "f"(x)); return r;
}
__device__ __forceinline__ void tf32_split(float x, uint32_t& hi, uint32_t& lo) {
    hi = f2tf32(x);
    lo = f2tf32(x - __uint_as_float(hi));
}
__device__ __forceinline__ void mma_tf32(float* c, const uint32_t* a, uint32_t b0, uint32_t b1) {
    asm volatile(
        "mma.sync.aligned.m16n8k8.row.col.f32.tf32.tf32.f32 "
        "{%0,%1,%2,%3}, {%4,%5,%6,%7}, {%8,%9}, {%0,%1,%2,%3};"
        : "+f"(c[0]), "+f"(c[1]), "+f"(c[2]), "+f"(c[3])
        : "r"(a[0]), "r"(a[1]), "r"(a[2]), "r"(a[3]), "r"(b0), "r"(b1));
}

// ---------------------------------------------------------------------------
// Kernel A1: split-K partial GEMM (unchanged).
// ---------------------------------------------------------------------------
__global__ __launch_bounds__(128) void gemm_partial(const float* __restrict__ A,
                                                    const float* __restrict__ Wm) {
    __shared__ __align__(16) float As[32][64];
    __shared__ __align__(16) float Ws[32][16];
    int tid = threadIdx.x;
    int jblk = blockIdx.x * 16;
    int kbase = blockIdx.y * KCHUNK;

    int an = tid >> 1;
    int ak = (tid & 1) * 16;
    int wj = tid >> 3;
    int wk = (tid & 7) * 4;
    int n0 = (tid & 15) * 4;
    int j0 = (tid >> 4) * 2;

    ull acc2[2][2];
    acc2[0][0] = acc2[0][1] = acc2[1][0] = acc2[1][1] = 0ULL;

    for (int k0 = kbase; k0 < kbase + KCHUNK; k0 += 32) {
        __syncthreads();
        const float4* ap = (const float4*)(A + (size_t)an * KDIM + k0 + ak);
#pragma unroll
        for (int v = 0; v < 4; v++) {
            float4 t = ap[v];
            As[ak + v * 4 + 0][an] = t.x;
            As[ak + v * 4 + 1][an] = t.y;
            As[ak + v * 4 + 2][an] = t.z;
            As[ak + v * 4 + 3][an] = t.w;
        }
        {
            int j = jblk + wj;
            float4 t = make_float4(0.f, 0.f, 0.f, 0.f);
            if (j < ATTN_LEN)
                t = *(const float4*)(Wm + (size_t)j * KDIM + k0 + wk);
            Ws[wk + 0][wj] = t.x;
            Ws[wk + 1][wj] = t.y;
            Ws[wk + 2][wj] = t.z;
            Ws[wk + 3][wj] = t.w;
        }
        __syncthreads();
#pragma unroll
        for (int kk = 0; kk < 32; kk++) {
            ulonglong2 a2 = *(const ulonglong2*)&As[kk][n0];
            float2 wf = *(const float2*)&Ws[kk][j0];
            ull wx = pack2(wf.x, wf.x);
            ull wy = pack2(wf.y, wf.y);
            acc2[0][0] = ffma2(a2.x, wx, acc2[0][0]);
            acc2[0][1] = ffma2(a2.x, wy, acc2[0][1]);
            acc2[1][0] = ffma2(a2.y, wx, acc2[1][0]);
            acc2[1][1] = ffma2(a2.y, wy, acc2[1][1]);
        }
    }
    float* outp = g_part + (size_t)blockIdx.y * NINST * ATTN_LEN;
#pragma unroll
    for (int p = 0; p < 2; p++) {
#pragma unroll
        for (int dj = 0; dj < 2; dj++) {
            int j = jblk + j0 + dj;
            if (j < ATTN_LEN) {
                float2 u = unpack2(acc2[p][dj]);
                outp[(size_t)(n0 + 2 * p)     * ATTN_LEN + j] = u.x;
                outp[(size_t)(n0 + 2 * p + 1) * ATTN_LEN + j] = u.y;
            }
        }
    }
}

// ---------------------------------------------------------------------------
// Kernel A2: deterministic reduce + bias.
// ---------------------------------------------------------------------------
__global__ __launch_bounds__(256) void reduce_attns(const float* __restrict__ bias) {
    int idx = blockIdx.x * 256 + threadIdx.x;
    if (idx >= NINST * ATTN_LEN) return;
    float s = 0.f;
#pragma unroll
    for (int p = 0; p < KSPLIT; p++) s += g_part[(size_t)p * NINST * ATTN_LEN + idx];
    g_attns[idx] = s + bias[idx % ATTN_LEN];
}

// ---------------------------------------------------------------------------
// Kernel A3: build per-lane B fragments for mma.sync, hi+lo packed in uint4.
// q (0..43): q<16 -> L1 (nt=q>>2, kt=q&3); q<32 -> L2; else L3 (nt 0..2).
// Entry [q][lane] = { hi(W[o][c]), hi(W[o][c+4]), lo(W[o][c]), lo(W[o][c+4]) }
//   o = nt*8 + (lane>>2), c = kt*8 + (lane&3)
// ---------------------------------------------------------------------------
__global__ __launch_bounds__(256) void build_bfrag() {
    int n = blockIdx.x;
    const float* row = g_attns + (size_t)n * ATTN_LEN;
    uint4* dst = g_bfrag + (size_t)n * BFRAG_INST;

    for (int e = threadIdx.x; e < BFRAG_INST; e += 256) {
        int lane = e & 31;
        int q = e >> 5;
        int layer, nt, kt;
        if (q < 16)      { layer = 0; nt = q >> 2;        kt = q & 3; }
        else if (q < 32) { layer = 1; nt = (q - 16) >> 2; kt = q & 3; }
        else             { layer = 2; nt = (q - 32) >> 2; kt = q & 3; }

        int o = nt * 8 + (lane >> 2);
        int c = kt * 8 + (lane & 3);

        float x0 = 0.f, x1 = 0.f;
        if (layer == 0) {
            x0 = row[o * 34 + (c + 2)];
            x1 = row[o * 34 + (c + 6)];
        } else if (layer == 1) {
            x0 = row[1120 + o * 32 + c];
            x1 = row[1120 + o * 32 + c + 4];
        } else if (o < NKP) {
            x0 = row[2176 + o * 32 + c];
            x1 = row[2176 + o * 32 + c + 4];
        }
        uint32_t h0, l0, h1, l1;
        tf32_split(x0, h0, l0);
        tf32_split(x1, h1, l1);
        dst[e] = make_uint4(h0, h1, l0, l1);
    }
}

// ---------------------------------------------------------------------------
// Kernel B: MLP via mma.sync tf32 (3xTF32). 8 warps/CTA, each warp = 32 px
// (2 m16-tiles). B fragments staged in smem per instance (shared by all
// warps); bases cached in per-warp smem tile; activations round-trip through
// per-warp smem. Dynamic smem: sB 22528 + bbuf 36864 + hbuf 36864 = 96256 B.
// ---------------------------------------------------------------------------
#define BSTRIDE 36
#define WBUF (32 * BSTRIDE)      // 1152 floats per warp

__device__ __forceinline__ void frags_from_buf(const float* buf, int lane, int mt,
                                               uint32_t* ah, uint32_t* al) {
    int g = lane >> 2, tig = lane & 3;
#pragma unroll
    for (int kt = 0; kt < 4; kt++) {
#pragma unroll
        for (int r = 0; r < 4; r++) {
            int rowi = 16 * mt + g + ((r & 1) << 3);
            int c = kt * 8 + tig + ((r >> 1) << 2);
            tf32_split(buf[rowi * BSTRIDE + c], ah[kt * 4 + r], al[kt * 4 + r]);
        }
    }
}

__global__ __launch_bounds__(256, 2) void mlp_mma(const float* __restrict__ bases_full,
                                                  const float* __restrict__ locations,
                                                  const float* __restrict__ sizes,
                                                  const int* __restrict__ fpn_levels,
                                                  float* __restrict__ out) {
    extern __shared__ unsigned char dsm[];
    uint4* sB   = (uint4*)dsm;                       // NQ*32 uint4
    float* bbuf = (float*)(dsm + NQ * 32 * 16);      // 8 warps * WBUF
    float* hbuf = bbuf + 8 * WBUF;

    int tid = threadIdx.x;
    int warp = tid >> 5;
    int lane = tid & 31;
    int g = lane >> 2, tig = lane & 3;

    int pxb = blockIdx.x * 256 + warp * 32;
    bool active = pxb < HW;                          // HW % 32 == 0

    float* bb = bbuf + warp * WBUF;
    float* hb = hbuf + warp * WBUF;

    float gxv[4], gyv[4];
    if (active) {
        // bases tile: [px(32)][ch(32)], stride 36 (conflict-free frag reads)
#pragma unroll 8
        for (int c = 0; c < 32; c++)
            bb[lane * BSTRIDE + c] = bases_full[(size_t)c * HW + pxb + lane];
#pragma unroll
        for (int r = 0; r < 4; r++) {
            int p = pxb + g + 8 * r;                 // row position 2*mt+half
            gxv[r] = (float)(p % WDIM) * 8.f + 4.f;
            gyv[r] = (float)(p / WDIM) * 8.f + 4.f;
        }
    }
    __syncwarp();

    int nbase = blockIdx.y * IPB;
    for (int ii = 0; ii < IPB; ii++) {
        int n = nbase + ii;
        // stage this instance's B fragments into smem (all threads)
        const uint4* src = g_bfrag + (size_t)n * BFRAG_INST;
        for (int i = tid; i < BFRAG_INST; i += 256) sB[i] = src[i];
        __syncthreads();

        if (active) {
            const float* row = g_attns + (size_t)n * ATTN_LEN;
            float invr = 1.f / sizes[fpn_levels[n]];
            float lx = locations[2 * n], ly = locations[2 * n + 1];

            uint32_t ah[2][16], al[2][16];
            float cc[2][4][4];

            // ================= layer 1 =================
            frags_from_buf(bb, lane, 0, ah[0], al[0]);
            frags_from_buf(bb, lane, 1, ah[1], al[1]);
#pragma unroll
            for (int mt = 0; mt < 2; mt++)
#pragma unroll
                for (int nt = 0; nt < 4; nt++)
#pragma unroll
                    for (int j = 0; j < 4; j++) cc[mt][nt][j] = 0.f;
#pragma unroll
            for (int nt = 0; nt < 4; nt++) {
#pragma unroll
                for (int kt = 0; kt < 4; kt++) {
                    uint4 f = sB[(nt * 4 + kt) * 32 + lane];
#pragma unroll
                    for (int mt = 0; mt < 2; mt++) {
                        mma_tf32(cc[mt][nt], &ah[mt][kt * 4], f.x, f.y);
                        mma_tf32(cc[mt][nt], &ah[mt][kt * 4], f.z, f.w);
                        mma_tf32(cc[mt][nt], &al[mt][kt * 4], f.x, f.y);
                    }
                }
            }
#pragma unroll
            for (int mt = 0; mt < 2; mt++) {
                float ox0 = (lx - gxv[2 * mt]) * invr,     oy0 = (ly - gyv[2 * mt]) * invr;
                float ox1 = (lx - gxv[2 * mt + 1]) * invr, oy1 = (ly - gyv[2 * mt + 1]) * invr;
                int r0 = 16 * mt + g, r1 = r0 + 8;
#pragma unroll
                for (int nt = 0; nt < 4; nt++) {
                    int o0 = nt * 8 + 2 * tig, o1 = o0 + 1;
                    float wx0 = row[o0 * 34], wy0 = row[o0 * 34 + 1], bb0 = row[1088 + o0];
                    float wx1 = row[o1 * 34], wy1 = row[o1 * 34 + 1], bb1 = row[1088 + o1];
                    hb[r0 * BSTRIDE + o0] = fmaxf(cc[mt][nt][0] + wx0 * ox0 + wy0 * oy0 + bb0, 0.f);
                    hb[r0 * BSTRIDE + o1] = fmaxf(cc[mt][nt][1] + wx1 * ox0 + wy1 * oy0 + bb1, 0.f);
                    hb[r1 * BSTRIDE + o0] = fmaxf(cc[mt][nt][2] + wx0 * ox1 + wy0 * oy1 + bb0, 0.f);
                    hb[r1 * BSTRIDE + o1] = fmaxf(cc[mt][nt][3] + wx1 * ox1 + wy1 * oy1 + bb1, 0.f);
                }
            }
            __syncwarp();

            // ================= layer 2 =================
            frags_from_buf(hb, lane, 0, ah[0], al[0]);
            frags_from_buf(hb, lane, 1, ah[1], al[1]);
            __syncwarp();
#pragma unroll
            for (int mt = 0; mt < 2; mt++)
#pragma unroll
                for (int nt = 0; nt < 4; nt++)
#pragma unroll
                    for (int j = 0; j < 4; j++) cc[mt][nt][j] = 0.f;
#pragma unroll
            for (int nt = 0; nt < 4; nt++) {
#pragma unroll
                for (int kt = 0; kt < 4; kt++) {
                    uint4 f = sB[(16 + nt * 4 + kt) * 32 + lane];
#pragma unroll
                    for (int mt = 0; mt < 2; mt++) {
                        mma_tf32(cc[mt][nt], &ah[mt][kt * 4], f.x, f.y);
                        mma_tf32(cc[mt][nt], &ah[mt][kt * 4], f.z, f.w);
                        mma_tf32(cc[mt][nt], &al[mt][kt * 4], f.x, f.y);
                    }
                }
            }
#pragma unroll
            for (int mt = 0; mt < 2; mt++) {
                int r0 = 16 * mt + g, r1 = r0 + 8;
#pragma unroll
                for (int nt = 0; nt < 4; nt++) {
                    int o0 = nt * 8 + 2 * tig, o1 = o0 + 1;
                    float bb0 = row[2144 + o0], bb1 = row[2144 + o1];
                    hb[r0 * BSTRIDE + o0] = fmaxf(cc[mt][nt][0] + bb0, 0.f);
                    hb[r0 * BSTRIDE + o1] = fmaxf(cc[mt][nt][1] + bb1, 0.f);
                    hb[r1 * BSTRIDE + o0] = fmaxf(cc[mt][nt][2] + bb0, 0.f);
                    hb[r1 * BSTRIDE + o1] = fmaxf(cc[mt][nt][3] + bb1, 0.f);
                }
            }
            __syncwarp();

            // ================= layer 3 (nt 0..2, write o<17) =================
            frags_from_buf(hb, lane, 0, ah[0], al[0]);
            frags_from_buf(hb, lane, 1, ah[1], al[1]);
#pragma unroll
            for (int mt = 0; mt < 2; mt++)
#pragma unroll
                for (int nt = 0; nt < 3; nt++)
#pragma unroll
                    for (int j = 0; j < 4; j++) cc[mt][nt][j] = 0.f;
#pragma unroll
            for (int nt = 0; nt < 3; nt++) {
#pragma unroll
                for (int kt = 0; kt < 4; kt++) {
                    uint4 f = sB[(32 + nt * 4 + kt) * 32 + lane];
#pragma unroll
                    for (int mt = 0; mt < 2; mt++) {
                        mma_tf32(cc[mt][nt], &ah[mt][kt * 4], f.x, f.y);
                        mma_tf32(cc[mt][nt], &ah[mt][kt * 4], f.z, f.w);
                        mma_tf32(cc[mt][nt], &al[mt][kt * 4], f.x, f.y);
                    }
                }
            }
            float* ob = out + (size_t)n * NKP * HW;
#pragma unroll
            for (int mt = 0; mt < 2; mt++) {
                int px0 = pxb + 16 * mt + g, px1 = px0 + 8;
#pragma unroll
                for (int nt = 0; nt < 3; nt++) {
                    int o0 = nt * 8 + 2 * tig, o1 = o0 + 1;
                    if (o0 < NKP) {
                        float bb0 = row[2720 + o0];
                        ob[(size_t)o0 * HW + px0] = cc[mt][nt][0] + bb0;
                        ob[(size_t)o0 * HW + px1] = cc[mt][nt][2] + bb0;
                    }
                    if (o1 < NKP) {
                        float bb1 = row[2720 + o1];
                        ob[(size_t)o1 * HW + px0] = cc[mt][nt][1] + bb1;
                        ob[(size_t)o1 * HW + px1] = cc[mt][nt][3] + bb1;
                    }
                }
            }
        }
        __syncthreads();   // sB reused next instance
    }
}

// ---------------------------------------------------------------------------
// Kernel C: per (n, kp) argmax over HW (first-index tie-break), then gather.
// ---------------------------------------------------------------------------
__global__ __launch_bounds__(256) void argmax_kernel(float* __restrict__ out,
                                                     const float* __restrict__ bases_full) {
    int pair = blockIdx.x;
    int k = pair % NKP;
    const float4* lg = (const float4*)(out + (size_t)pair * HW);
    int tid = threadIdx.x;

    float best = -3.4e38f;
    int bi = 0;
    for (int q = tid; q < HW / 4; q += 256) {
        float4 v = lg[q];
        int i0 = q * 4;
        if (v.x > best) { best = v.x; bi = i0; }
        if (v.y > best) { best = v.y; bi = i0 + 1; }
        if (v.z > best) { best = v.z; bi = i0 + 2; }
        if (v.w > best) { best = v.w; bi = i0 + 3; }
    }

    __shared__ float sv[256];
    __shared__ int si[256];
    sv[tid] = best;
    si[tid] = bi;
    __syncthreads();
#pragma unroll
    for (int s = 128; s > 0; s >>= 1) {
        if (tid < s) {
            float ov = sv[tid + s]; int oi = si[tid + s];
            if (ov > sv[tid] || (ov == sv[tid] && oi < si[tid])) {
                sv[tid] = ov; si[tid] = oi;
            }
        }
        __syncthreads();
    }
    if (tid == 0) {
        int i = si[0];
        float gx = (float)(i % WDIM) * 8.f + 4.f;
        float gy = (float)(i / WDIM) * 8.f + 4.f;
        float* kp = out + (size_t)NINST * NKP * HW + (size_t)pair * 2;
        kp[0] = bases_full[(size_t)(NB + 2 * k)     * HW + i] + gx;
        kp[1] = bases_full[(size_t)(NB + 2 * k + 1) * HW + i] + gy;
    }
}

// ---------------------------------------------------------------------------
extern "C" void kernel_launch(void* const* d_in, const int* in_sizes, int n_in,
                              void* d_out, int out_size) {
    const float* bases_full = (const float*)d_in[0];
    const float* top_feats  = (const float*)d_in[1];
    const float* locations  = (const float*)d_in[2];
    const float* atten_W    = (const float*)d_in[3];
    const float* atten_b    = (const float*)d_in[4];
    const float* sizes      = (const float*)d_in[5];
    const int*   fpn_levels = (const int*)d_in[6];
    float* out = (float*)d_out;

    const int DSMEM = NQ * 32 * 16 + 2 * 8 * WBUF * 4;   // 22528 + 73728 = 96256
    cudaFuncSetAttribute(mlp_mma, cudaFuncAttributeMaxDynamicSharedMemorySize, DSMEM);

    gemm_partial<<<dim3((ATTN_LEN + 15) / 16, KSPLIT), 128>>>(top_feats, atten_W);
    reduce_attns<<<(NINST * ATTN_LEN + 255) / 256, 256>>>(atten_b);
    build_bfrag<<<NINST, 256>>>();

    mlp_mma<<<dim3(GX, IGY), 256, DSMEM>>>(bases_full, locations, sizes, fpn_levels, out);

    argmax_kernel<<<NINST * NKP, 256>>>(out, bases_full);
}